// round 2
// baseline (speedup 1.0000x reference)
#include <cuda_runtime.h>
#include <cstdint>

#define MAXN 40000
#define FDIM 128

// Static scratch (no allocation allowed)
__device__ float g_agg1[MAXN * FDIM];
__device__ float g_agg2[MAXN * FDIM];
__device__ float g_h1  [MAXN * FDIM];
__device__ float g_h2  [MAXN * FDIM];
__device__ float g_stats [2 * MAXN];  // [0,N): deg   [N,2N): sum_w
__device__ float g_scales[2 * MAXN];  // [0,N): sm    [N,2N): sh

// ---------------------------------------------------------------------------
// Zero both agg buffers + stats in one launch.
__global__ void zero_all_kernel(int n) {
    int tid = blockIdx.x * blockDim.x + threadIdx.x;
    int stride = gridDim.x * blockDim.x;
    int nf4 = n * (FDIM / 4);
    float4 z = make_float4(0.f, 0.f, 0.f, 0.f);
    float4* p1 = reinterpret_cast<float4*>(g_agg1);
    float4* p2 = reinterpret_cast<float4*>(g_agg2);
    for (int i = tid; i < nf4; i += stride) { p1[i] = z; p2[i] = z; }
    for (int i = tid; i < 2 * n; i += stride) g_stats[i] = 0.f;
}

__global__ void edge_stats_kernel(const int* __restrict__ dst,
                                  const float* __restrict__ w,
                                  int E, int n) {
    int e = blockIdx.x * blockDim.x + threadIdx.x;
    if (e >= E) return;
    int d = dst[e];
    atomicAdd(&g_stats[d], 1.0f);
    atomicAdd(&g_stats[n + d], w[e]);
}

__global__ void scales_kernel(int n) {
    int i = blockIdx.x * blockDim.x + threadIdx.x;
    if (i >= n) return;
    float dg = g_stats[i];
    float sw = g_stats[n + i];
    float smv = 0.f, shv = 0.f;
    if (dg > 0.f) {
        float inv = 1.0f / (dg + 1.0f);
        shv = inv;
        float swp = (sw == 0.f) ? 1.f : sw;
        smv = dg * inv / swp;
    }
    g_scales[i]     = smv;
    g_scales[n + i] = shv;
}

// Warp-per-edge weighted gather-scatter: agg[dst] += h[src] * w
__global__ void __launch_bounds__(256)
agg_kernel(const float4* __restrict__ h,
           const int* __restrict__ src, const int* __restrict__ dst,
           const float* __restrict__ w, float* __restrict__ agg, int E) {
    int gw   = (blockIdx.x * blockDim.x + threadIdx.x) >> 5;
    int lane = threadIdx.x & 31;
    if (gw >= E) return;
    int s = src[gw];
    int d = dst[gw];
    float wt = w[gw];
    float4 v = h[s * 32 + lane];
    v.x *= wt; v.y *= wt; v.z *= wt; v.w *= wt;
    float* addr = &agg[d * FDIM + lane * 4];
    asm volatile("red.global.add.v4.f32 [%0], {%1,%2,%3,%4};"
                 :: "l"(addr), "f"(v.x), "f"(v.y), "f"(v.z), "f"(v.w)
                 : "memory");
}

// ---------------------------------------------------------------------------
// 3xTF32 tensor-core update: X = sm*agg + sh*hin ; hout = relu(X @ W^T + b)
// Tile: 64 nodes x 128 outs. 8 warps, each m32 x n32 via m16n8k8 mma.
// Smem pitches chosen for conflict-free fragment loads:
//   Xs pitch 132 -> A-frag banks 4*grp+tig (all distinct)
//   Ws pitch 136 -> B-frag banks 8*tig+grp (all distinct)

#define TM 64
#define XPITCH 132
#define WPITCH 136

__device__ __forceinline__ uint32_t f2tf32(float v) {
    uint32_t r;
    asm("cvt.rna.tf32.f32 %0, %1;" : "=r"(r) : "f"(v));
    return r;
}

__device__ __forceinline__ void mma_tf32(float acc[4],
                                         const uint32_t a[4],
                                         uint32_t b0, uint32_t b1) {
    asm volatile(
        "mma.sync.aligned.m16n8k8.row.col.f32.tf32.tf32.f32 "
        "{%0,%1,%2,%3}, {%4,%5,%6,%7}, {%8,%9}, {%0,%1,%2,%3};"
        : "+f"(acc[0]), "+f"(acc[1]), "+f"(acc[2]), "+f"(acc[3])
        : "r"(a[0]), "r"(a[1]), "r"(a[2]), "r"(a[3]), "r"(b0), "r"(b1));
}

__global__ void __launch_bounds__(256)
update_kernel(const float* __restrict__ hin, const float* __restrict__ agg,
              const float* __restrict__ W,   const float* __restrict__ bias,
              float* __restrict__ hout, int n) {
    extern __shared__ float smem[];
    float* Wh = smem;                               // [128][WPITCH]
    float* Wl = Wh + FDIM * WPITCH;
    float* Xh = Wl + FDIM * WPITCH;                 // [TM][XPITCH]
    float* Xl = Xh + TM * XPITCH;

    int tid = threadIdx.x;
    // Load W transposed + tf32 split (once per block)
    for (int i = tid; i < FDIM * FDIM; i += 256) {
        int o = i >> 7, k = i & 127;
        float v = W[i];
        uint32_t hi = f2tf32(v);
        float hif = __uint_as_float(hi);
        uint32_t lo = f2tf32(v - hif);
        Wh[k * WPITCH + o] = hif;
        Wl[k * WPITCH + o] = __uint_as_float(lo);
    }

    int warp = tid >> 5;
    int lane = tid & 31;
    int grp  = lane >> 2;       // 0..7
    int tig  = lane & 3;        // 0..3
    int wm   = warp >> 2;       // 0..1 -> m offset wm*32
    int wn   = warp & 3;        // 0..3 -> n offset wn*32

    int ntiles = (n + TM - 1) / TM;
    for (int tile = blockIdx.x; tile < ntiles; tile += gridDim.x) {
        __syncthreads();
        int n0 = tile * TM;
        // Fill Xs (combine + tf32 split)
        for (int i = tid; i < TM * FDIM; i += 256) {
            int nl = i >> 7, k = i & 127;
            int node = n0 + nl;
            float v = 0.f;
            if (node < n)
                v = g_scales[node]     * agg[node * FDIM + k]
                  + g_scales[n + node] * hin[node * FDIM + k];
            uint32_t hi = f2tf32(v);
            float hif = __uint_as_float(hi);
            uint32_t lo = f2tf32(v - hif);
            Xh[nl * XPITCH + k] = hif;
            Xl[nl * XPITCH + k] = __uint_as_float(lo);
        }
        __syncthreads();

        // acc[mb][nb][4]: mb in 0..1 (m16 blocks), nb in 0..3 (n8 blocks)
        float acc[2][4][4];
#pragma unroll
        for (int nb = 0; nb < 4; nb++) {
            int c = wn * 32 + nb * 8 + 2 * tig;
            float b0 = bias[c], b1 = bias[c + 1];
#pragma unroll
            for (int mb = 0; mb < 2; mb++) {
                acc[mb][nb][0] = b0; acc[mb][nb][1] = b1;
                acc[mb][nb][2] = b0; acc[mb][nb][3] = b1;
            }
        }

#pragma unroll 4
        for (int k0 = 0; k0 < FDIM; k0 += 8) {
            uint32_t ah[2][4], al[2][4];
#pragma unroll
            for (int mb = 0; mb < 2; mb++) {
                int r = wm * 32 + mb * 16 + grp;
                const float* pah = &Xh[r * XPITCH + k0 + tig];
                const float* pal = &Xl[r * XPITCH + k0 + tig];
                ah[mb][0] = __float_as_uint(pah[0]);
                ah[mb][1] = __float_as_uint(pah[8 * XPITCH]);
                ah[mb][2] = __float_as_uint(pah[4]);
                ah[mb][3] = __float_as_uint(pah[8 * XPITCH + 4]);
                al[mb][0] = __float_as_uint(pal[0]);
                al[mb][1] = __float_as_uint(pal[8 * XPITCH]);
                al[mb][2] = __float_as_uint(pal[4]);
                al[mb][3] = __float_as_uint(pal[8 * XPITCH + 4]);
            }
#pragma unroll
            for (int nb = 0; nb < 4; nb++) {
                int c = wn * 32 + nb * 8 + grp;
                const float* pbh = &Wh[(k0 + tig) * WPITCH + c];
                const float* pbl = &Wl[(k0 + tig) * WPITCH + c];
                uint32_t bh0 = __float_as_uint(pbh[0]);
                uint32_t bh1 = __float_as_uint(pbh[4 * WPITCH]);
                uint32_t bl0 = __float_as_uint(pbl[0]);
                uint32_t bl1 = __float_as_uint(pbl[4 * WPITCH]);
#pragma unroll
                for (int mb = 0; mb < 2; mb++) {
                    mma_tf32(acc[mb][nb], ah[mb], bh0, bh1);  // hi*hi
                    mma_tf32(acc[mb][nb], ah[mb], bl0, bl1);  // hi*lo
                    mma_tf32(acc[mb][nb], al[mb], bh0, bh1);  // lo*hi
                }
            }
        }

        // Epilogue: relu + store (float2 per row fragment)
#pragma unroll
        for (int mb = 0; mb < 2; mb++) {
            int r0 = n0 + wm * 32 + mb * 16 + grp;
            int r1 = r0 + 8;
#pragma unroll
            for (int nb = 0; nb < 4; nb++) {
                int c = wn * 32 + nb * 8 + 2 * tig;
                if (r0 < n) {
                    float2 v0 = make_float2(fmaxf(acc[mb][nb][0], 0.f),
                                            fmaxf(acc[mb][nb][1], 0.f));
                    *reinterpret_cast<float2*>(&hout[r0 * FDIM + c]) = v0;
                }
                if (r1 < n) {
                    float2 v1 = make_float2(fmaxf(acc[mb][nb][2], 0.f),
                                            fmaxf(acc[mb][nb][3], 0.f));
                    *reinterpret_cast<float2*>(&hout[r1 * FDIM + c]) = v1;
                }
            }
        }
    }
}

// Final classifier: out = h2 @ Wo^T + bo   ([N,128] x [32,128]^T -> [N,32])
__global__ void __launch_bounds__(256)
out_kernel(const float4* __restrict__ h2,
           const float* __restrict__ Wo, const float* __restrict__ bo,
           float* __restrict__ out, int n) {
    __shared__ float Wos[FDIM * 32];  // [k][o]
    int tid = threadIdx.x;
    for (int i = tid; i < 32 * FDIM; i += 256) {
        int o = i >> 7, k = i & 127;
        Wos[k * 32 + o] = Wo[i];
    }
    __syncthreads();

    int lane = tid & 31;
    int wp   = tid >> 5;
    float bias = bo[lane];
    for (int node = blockIdx.x * 8 + wp; node < n; node += gridDim.x * 8) {
        float4 x = h2[node * 32 + lane];
        float acc = bias;
#pragma unroll
        for (int j = 0; j < 32; j++) {
            float a = __shfl_sync(0xffffffffu, x.x, j);
            float b = __shfl_sync(0xffffffffu, x.y, j);
            float c = __shfl_sync(0xffffffffu, x.z, j);
            float d = __shfl_sync(0xffffffffu, x.w, j);
            int k = j << 2;
            acc += a * Wos[(k + 0) * 32 + lane];
            acc += b * Wos[(k + 1) * 32 + lane];
            acc += c * Wos[(k + 2) * 32 + lane];
            acc += d * Wos[(k + 3) * 32 + lane];
        }
        out[node * 32 + lane] = acc;
    }
}

// ---------------------------------------------------------------------------
extern "C" void kernel_launch(void* const* d_in, const int* in_sizes, int n_in,
                              void* d_out, int out_size) {
    const float* features = (const float*)d_in[0];
    const int*   src      = (const int*)  d_in[1];
    const int*   dst      = (const int*)  d_in[2];
    const float* weight   = (const float*)d_in[3];
    const float* W1       = (const float*)d_in[4];
    const float* b1       = (const float*)d_in[5];
    const float* W2       = (const float*)d_in[6];
    const float* b2       = (const float*)d_in[7];
    const float* Wo       = (const float*)d_in[8];
    const float* bo       = (const float*)d_in[9];
    float* out = (float*)d_out;

    int N = in_sizes[0] / FDIM;
    int E = in_sizes[1];

    void *pa1_v, *pa2_v, *ph1_v, *ph2_v;
    cudaGetSymbolAddress(&pa1_v, g_agg1);
    cudaGetSymbolAddress(&pa2_v, g_agg2);
    cudaGetSymbolAddress(&ph1_v, g_h1);
    cudaGetSymbolAddress(&ph2_v, g_h2);
    float* pa1 = (float*)pa1_v;
    float* pa2 = (float*)pa2_v;
    float* ph1 = (float*)ph1_v;
    float* ph2 = (float*)ph2_v;

    const int smem_bytes =
        (2 * FDIM * WPITCH + 2 * TM * XPITCH) * (int)sizeof(float);  // 206848
    cudaFuncSetAttribute(update_kernel,
                         cudaFuncAttributeMaxDynamicSharedMemorySize, smem_bytes);

    zero_all_kernel<<<1024, 256>>>(N);
    edge_stats_kernel<<<(E + 255) / 256, 256>>>(dst, weight, E, N);
    scales_kernel<<<(N + 255) / 256, 256>>>(N);

    // Layer 1
    agg_kernel<<<(E + 7) / 8, 256>>>((const float4*)features, src, dst, weight, pa1, E);
    update_kernel<<<148, 256, smem_bytes>>>(features, pa1, W1, b1, ph1, N);

    // Layer 2
    agg_kernel<<<(E + 7) / 8, 256>>>((const float4*)ph1, src, dst, weight, pa2, E);
    update_kernel<<<148, 256, smem_bytes>>>(ph1, pa2, W2, b2, ph2, N);

    // Classifier
    out_kernel<<<2048, 256>>>((const float4*)ph2, Wo, bo, out, N);
}